// round 3
// baseline (speedup 1.0000x reference)
#include <cuda_runtime.h>

// Capsule routing, restructured:
//   round0: s1 = (u@w)/O + bias ; v1 = squash(s1)
//   round1: s2[b,o] = sum_i u[b,i] w[i,o] softmax_o(u[b,i] w[i,o] v1[b,o]) + bias ; v2 = squash(s2)
//   round2: same with Vacc = v1+v2 ; out = squash(...)
// Softmax kernel: warp = (b, 32-i chunk); lane owns 32 o; V held in REGISTERS
// (loaded once). Packed f32x2 math; exp = MUFU ex2 (24/32) + scalar FFMA-imm
// deg-4 poly (8/32) to balance FMA vs MUFU pipes. Results REDG into g_s.
// Mode-0 GEMV kernel: warp = 8 b x 128 o (8x less w traffic).
// Fused reduce+squash (1024 thr/block) rezeroes g_s for the next round.

#define BB 64
#define II 1024
#define OO 1024
#define ICHUNK 32
#define NCHUNK (II / ICHUNK)   // 32
#define WPB 8
#define LOG2E 1.4426950408889634f

typedef unsigned long long u64;

__device__ float g_s[BB * OO];     // per-round accumulator (kept zero between rounds)
__device__ float g_vacc[BB * OO];  // accumulated v (pre-scaled by LOG2E)

__device__ __forceinline__ float ex2a(float x) {
    float r; asm("ex2.approx.f32 %0, %1;" : "=f"(r) : "f"(x)); return r;
}
__device__ __forceinline__ float rcpa(float x) {
    float r; asm("rcp.approx.f32 %0, %1;" : "=f"(r) : "f"(x)); return r;
}
__device__ __forceinline__ u64 pk(float x, float y) {
    u64 r; asm("mov.b64 %0, {%1, %2};" : "=l"(r) : "f"(x), "f"(y)); return r;
}
__device__ __forceinline__ void upk(float& x, float& y, u64 v) {
    asm("mov.b64 {%0, %1}, %2;" : "=f"(x), "=f"(y) : "l"(v));
}
__device__ __forceinline__ u64 mul2(u64 a, u64 b) {
    u64 r; asm("mul.rn.f32x2 %0, %1, %2;" : "=l"(r) : "l"(a), "l"(b)); return r;
}
__device__ __forceinline__ u64 add2(u64 a, u64 b) {
    u64 r; asm("add.rn.f32x2 %0, %1, %2;" : "=l"(r) : "l"(a), "l"(b)); return r;
}
__device__ __forceinline__ u64 fma2(u64 a, u64 b, u64 c) {
    u64 r; asm("fma.rn.f32x2 %0, %1, %2, %3;" : "=l"(r) : "l"(a), "l"(b), "l"(c)); return r;
}

// scalar exp2 for small |x| (deg-4 Taylor); immediates -> FFMA-imm (rt 1)
__device__ __forceinline__ float exp2s(float x) {
    float r = fmaf(x, 0.00961813f, 0.05550411f);
    r = fmaf(r, x, 0.24022651f);
    r = fmaf(r, x, 0.69314718f);
    return fmaf(r, x, 1.0f);
}

// ---------------- softmax routing sweep (rounds 1 and 2) ----------------
__global__ void __launch_bounds__(WPB * 32, 2)
softmax_kernel(const float* __restrict__ u, const float* __restrict__ w) {
    const int warp  = threadIdx.x >> 5;
    const int lane  = threadIdx.x & 31;
    const int chunk = blockIdx.x;              // 0..31
    const int b     = blockIdx.y * WPB + warp; // 0..63
    const int i0    = chunk * ICHUNK;

    // V (= (v1[+v2]) * LOG2E) in registers, loaded once: lane owns o = 128k+4lane+j
    u64 V[16];
    {
        const float4* v4p = reinterpret_cast<const float4*>(&g_vacc[b * OO]);
#pragma unroll
        for (int k = 0; k < 8; k++) {
            float4 v = v4p[k * 32 + lane];
            V[2 * k + 0] = pk(v.x, v.y);
            V[2 * k + 1] = pk(v.z, v.w);
        }
    }

    u64 acc[16];
#pragma unroll
    for (int m = 0; m < 16; m++) acc[m] = 0ull;

    const float au = u[b * II + i0 + lane];

#pragma unroll 1
    for (int ii = 0; ii < ICHUNK; ii++) {
        const float a = __shfl_sync(0xffffffffu, au, ii);
        const u64 a2 = pk(a, a);
        const float4* wrow = reinterpret_cast<const float4*>(w + (size_t)(i0 + ii) * OO);

        u64 p[16];
        u64 esum2 = 0ull;
#pragma unroll
        for (int k = 0; k < 8; k++) {
            float4 wv = wrow[k * 32 + lane];
            u64 t01 = mul2(a2, pk(wv.x, wv.y));
            u64 t23 = mul2(a2, pk(wv.z, wv.w));
            u64 l01 = mul2(t01, V[2 * k + 0]);
            u64 l23 = mul2(t23, V[2 * k + 1]);
            u64 e01, e23;
            float x0, x1, y0, y1;
            upk(x0, x1, l01); upk(y0, y1, l23);
            if (k < 6) {   // MUFU path: 24 of 32 elems
                e01 = pk(ex2a(x0), ex2a(x1));
                e23 = pk(ex2a(y0), ex2a(y1));
            } else {       // FMA-pipe poly path: 8 of 32 elems
                e01 = pk(exp2s(x0), exp2s(x1));
                e23 = pk(exp2s(y0), exp2s(y1));
            }
            esum2 = add2(esum2, add2(e01, e23));
            p[2 * k + 0] = mul2(t01, e01);
            p[2 * k + 1] = mul2(t23, e23);
        }
        float e0, e1;
        upk(e0, e1, esum2);
        float es = e0 + e1;
#pragma unroll
        for (int s = 16; s > 0; s >>= 1)
            es += __shfl_xor_sync(0xffffffffu, es, s);
        const float rZ = rcpa(es);
        const u64 rZ2 = pk(rZ, rZ);
#pragma unroll
        for (int m = 0; m < 16; m++)
            acc[m] = fma2(p[m], rZ2, acc[m]);
    }

    float* gs = &g_s[b * OO];
#pragma unroll
    for (int k = 0; k < 8; k++) {
        float f0, f1, f2, f3;
        upk(f0, f1, acc[2 * k + 0]);
        upk(f2, f3, acc[2 * k + 1]);
        const int o = 128 * k + 4 * lane;
        atomicAdd(&gs[o + 0], f0);
        atomicAdd(&gs[o + 1], f1);
        atomicAdd(&gs[o + 2], f2);
        atomicAdd(&gs[o + 3], f3);
    }
}

// ---------------- round-0 GEMV: s = (u @ w)/O, 8-b-blocked ----------------
// warp handles 8 b (b = warp*8+j) x 128 o (o = og*128 + 4*lane + t), i in chunks of 64
__global__ void __launch_bounds__(256, 2)
gemv_kernel(const float* __restrict__ u, const float* __restrict__ w) {
    const int warp  = threadIdx.x >> 5;
    const int lane  = threadIdx.x & 31;
    const int chunk = blockIdx.x;   // 0..15 (64 i each)
    const int og    = blockIdx.y;   // 0..7
    const int i0    = chunk * 64;
    const int ocol  = og * 128 + 4 * lane;

    u64 acc[16];
#pragma unroll
    for (int m = 0; m < 16; m++) acc[m] = 0ull;

#pragma unroll 1
    for (int half = 0; half < 2; half++) {
        const int ih = i0 + half * 32;
        float au[8];
#pragma unroll
        for (int j = 0; j < 8; j++)
            au[j] = u[(size_t)(warp * 8 + j) * II + ih + lane];

#pragma unroll 1
        for (int ii = 0; ii < 32; ii++) {
            const float4 wv = *reinterpret_cast<const float4*>(
                w + (size_t)(ih + ii) * OO + ocol);
            const u64 w01 = pk(wv.x, wv.y);
            const u64 w23 = pk(wv.z, wv.w);
#pragma unroll
            for (int j = 0; j < 8; j++) {
                const float a = __shfl_sync(0xffffffffu, au[j], ii);
                const u64 a2 = pk(a, a);
                acc[2 * j + 0] = fma2(a2, w01, acc[2 * j + 0]);
                acc[2 * j + 1] = fma2(a2, w23, acc[2 * j + 1]);
            }
        }
    }

    const u64 inv = pk(1.0f / OO, 1.0f / OO);
#pragma unroll
    for (int j = 0; j < 8; j++) {
        u64 a01 = mul2(acc[2 * j + 0], inv);
        u64 a23 = mul2(acc[2 * j + 1], inv);
        float f0, f1, f2, f3;
        upk(f0, f1, a01);
        upk(f2, f3, a23);
        float* gs = &g_s[(size_t)(warp * 8 + j) * OO + ocol];
        atomicAdd(&gs[0], f0);
        atomicAdd(&gs[1], f1);
        atomicAdd(&gs[2], f2);
        atomicAdd(&gs[3], f3);
    }
}

// -------- fused reduce + bias + squash; rezeroes g_s for the next round --------
__global__ void __launch_bounds__(1024, 1)
reduce_squash_kernel(const float* __restrict__ bias, float* __restrict__ outp,
                     float scale, int accumulate) {
    const int b    = blockIdx.x;
    const int o    = threadIdx.x;
    const int lane = o & 31;
    const int wid  = o >> 5;

    float x = g_s[b * OO + o] + bias[o];
    g_s[b * OO + o] = 0.0f;

    float ss = x * x;
#pragma unroll
    for (int s = 16; s > 0; s >>= 1)
        ss += __shfl_xor_sync(0xffffffffu, ss, s);

    __shared__ float red[32];
    if (lane == 0) red[wid] = ss;
    __syncthreads();
    if (wid == 0) {
        float r = red[lane];
#pragma unroll
        for (int s = 16; s > 0; s >>= 1)
            r += __shfl_xor_sync(0xffffffffu, r, s);
        if (lane == 0) red[0] = r;
    }
    __syncthreads();

    const float n2 = red[0];
    const float n = sqrtf(n2);
    const float f = n2 / ((1.0f + n2) * (n + 1e-5f)) * scale;

    float* dst = outp ? outp : g_vacc;
    float val = x * f;
    if (accumulate) val += dst[b * OO + o];
    dst[b * OO + o] = val;
}

extern "C" void kernel_launch(void* const* d_in, const int* in_sizes, int n_in,
                              void* d_out, int out_size) {
    const float* u    = (const float*)d_in[0];
    const float* w    = (const float*)d_in[1];
    const float* bias = (const float*)d_in[2];
    float* out = (float*)d_out;

    // round 0: uniform coupling -> v1 (stored as v1*LOG2E)
    gemv_kernel<<<dim3(16, 8), 256>>>(u, w);
    reduce_squash_kernel<<<BB, 1024>>>(bias, nullptr, LOG2E, 0);

    // round 1: softmax routing with v1 -> g_vacc += v2*LOG2E
    softmax_kernel<<<dim3(NCHUNK, BB / WPB), WPB * 32>>>(u, w);
    reduce_squash_kernel<<<BB, 1024>>>(bias, nullptr, LOG2E, 1);

    // round 2: softmax routing with v1+v2 -> final squash to output
    softmax_kernel<<<dim3(NCHUNK, BB / WPB), WPB * 32>>>(u, w);
    reduce_squash_kernel<<<BB, 1024>>>(bias, out, 1.0f, 0);
}